// round 4
// baseline (speedup 1.0000x reference)
#include <cuda_runtime.h>
#include <cstdint>

// BoothGroupQuant, round 4: one thread = one group of 16; parallel tie-rank
// (no serial chain), no aliased local arrays, occupancy-capped regs.
//
//   q  = clip(round(x*128), -32768, 32767)
//   nz = ((3q ^ q) >> 1) & 0xFFFF   (NAF nonzero-digit positions, fits 16b)
//   M  = ((q & ~3q) >> 1) & 0xFFFF  (-1 digit positions)
//   keep 8 largest-exponent digits per group (threshold exponent t via
//   CSA bit-plane counts + 4-probe binary search; ties at t in ascending
//   element order via prefix-popcount of the level-t bit word B).
//   v = k - 2*(k & M);  out = v * 2^-7.

#define CSA(s, c, a, b, d)            \
    do {                              \
        unsigned _x = (a) ^ (b);      \
        s = _x ^ (d);                 \
        c = ((a) & (b)) | (_x & (d)); \
    } while (0)

__device__ __forceinline__ unsigned mkmask(float v) {
    int q = __float2int_rn(v * 128.0f);
    q = max(-32768, min(32767, q));
    unsigned u  = (unsigned)q;
    unsigned u3 = u * 3u;
    unsigned nz = ((u3 ^ u) >> 1) & 0xFFFFu;
    unsigned m  = ((u & ~u3) >> 1) & 0xFFFFu;
    return nz | (m << 16);
}

__global__ void __launch_bounds__(128, 10)
booth_group_quant_kernel(const float4* __restrict__ x,
                         float4* __restrict__ out,
                         int ngroups) {
    const int g = blockIdx.x * blockDim.x + threadIdx.x;
    if (g >= ngroups) return;

    const float4* __restrict__ xv = x + (size_t)g * 4;
    float4 f0 = xv[0], f1 = xv[1], f2 = xv[2], f3 = xv[3];

    unsigned pk[16];
    pk[0]  = mkmask(f0.x); pk[1]  = mkmask(f0.y);
    pk[2]  = mkmask(f0.z); pk[3]  = mkmask(f0.w);
    pk[4]  = mkmask(f1.x); pk[5]  = mkmask(f1.y);
    pk[6]  = mkmask(f1.z); pk[7]  = mkmask(f1.w);
    pk[8]  = mkmask(f2.x); pk[9]  = mkmask(f2.y);
    pk[10] = mkmask(f2.z); pk[11] = mkmask(f2.w);
    pk[12] = mkmask(f3.x); pk[13] = mkmask(f3.y);
    pk[14] = mkmask(f3.z); pk[15] = mkmask(f3.w);

    // ---- CSA tree: per-exponent column counts as 5 bit-planes ----
    unsigned P0, P1, P2, P3, P4;
    {
        unsigned s1, c1, s2, c2, s3, c3, s4, c4, s5, c5, s6, c6, s7, c7;
        CSA(s1, c1, pk[0], pk[1], pk[2]);
        CSA(s2, c2, pk[3], pk[4], pk[5]);
        CSA(s3, c3, pk[6], pk[7], pk[8]);
        CSA(s4, c4, pk[9], pk[10], pk[11]);
        CSA(s5, c5, pk[12], pk[13], pk[14]);
        CSA(s6, c6, s1, s2, s3);
        CSA(s7, c7, s4, s5, pk[15]);
        P0 = s6 ^ s7;
        unsigned h1 = s6 & s7;
        unsigned sA, cA, sB, cB, sC, cC, sD, cD;
        CSA(sA, cA, c1, c2, c3);
        CSA(sB, cB, c4, c5, c6);
        CSA(sC, cC, c7, h1, sA);
        P1 = sB ^ sC;
        unsigned h2 = sB & sC;
        CSA(sD, cD, cA, cB, cC);
        P2 = sD ^ h2;
        unsigned h3 = sD & h2;
        P3 = cD ^ h3;
        P4 = cD & h3;
        P0 &= 0xFFFFu; P1 &= 0xFFFFu; P2 &= 0xFFFFu; P3 &= 0xFFFFu; P4 &= 0xFFFFu;
    }

    // ---- binary search: largest t in [0,15] with S(t) >= 8 ----
    int lo = 0, hi = 16, chi = 0;
#pragma unroll
    for (int it = 0; it < 4; ++it) {
        int m = (lo + hi) >> 1;
        int s = __popc(P0 >> m) + 2 * __popc(P1 >> m) + 4 * __popc(P2 >> m) +
                8 * __popc(P3 >> m) + 16 * __popc(P4 >> m);
        if (s >= 8) lo = m; else { hi = m; chi = s; }
    }
    const int t = lo;
    const int r = 8 - chi;                              // slots at level t
    const unsigned hm = (0xFFFFu << (t + 1)) & 0xFFFFu; // exponents > t

    // ---- level-t bit word across elements (parallel build) ----
    unsigned B = 0;
#pragma unroll
    for (int j = 0; j < 16; ++j) B |= ((pk[j] >> t) & 1u) << j;

    // ---- per-element keep decision (independent: prefix popc vs r) ----
#define RECON(j)                                                        \
    ({                                                                  \
        unsigned _w   = pk[j];                                          \
        unsigned _bt  = (B >> (j)) & 1u;                                \
        int _pc       = __popc(B & ((1u << (j)) - 1u));                 \
        unsigned _tk  = (_pc < r) ? _bt : 0u;                           \
        unsigned _k   = (_w & hm) | (_tk << t);                         \
        unsigned _km  = _k & (_w >> 16);                                \
        (float)((int)_k - 2 * (int)_km) * 0.0078125f;                   \
    })

    float4* __restrict__ ov = out + (size_t)g * 4;
    {
        float4 o;
        o.x = RECON(0);  o.y = RECON(1);  o.z = RECON(2);  o.w = RECON(3);
        ov[0] = o;
        o.x = RECON(4);  o.y = RECON(5);  o.z = RECON(6);  o.w = RECON(7);
        ov[1] = o;
        o.x = RECON(8);  o.y = RECON(9);  o.z = RECON(10); o.w = RECON(11);
        ov[2] = o;
        o.x = RECON(12); o.y = RECON(13); o.z = RECON(14); o.w = RECON(15);
        ov[3] = o;
    }
#undef RECON
}

extern "C" void kernel_launch(void* const* d_in, const int* in_sizes, int n_in,
                              void* d_out, int out_size) {
    const float* x = (const float*)d_in[0];
    float* out = (float*)d_out;
    int n = in_sizes[0];
    int ngroups = n >> 4;
    int block = 128;
    int grid = (ngroups + block - 1) / block;
    booth_group_quant_kernel<<<grid, block>>>(
        (const float4*)x, (float4*)out, ngroups);
}

// round 5
// speedup vs baseline: 1.1763x; 1.1763x over previous
#include <cuda_runtime.h>
#include <cstdint>

// BoothGroupQuant, round 5: thread = group of 16 (R3 core, proven 11.4us),
// plus: smem-staged fully-coalesced gmem I/O (XOR-swizzled, bank-conflict-
// free), parallel tie-rank (no serial chain), magic-constant round-to-int,
// no register cap (R4's cap caused spills and regressed).
//
//   q  = clip(round_half_even(x*128), -32768, 32767)
//   nz = ((3q ^ q) >> 1) & 0xFFFF    (NAF nonzero-digit positions)
//   M  = ((q & ~3q) >> 1) & 0xFFFF   (-1 digit positions)
//   keep 8 largest-exponent digits/group (ties at threshold exponent t in
//   ascending element order); v = k - 2*(k&M); out = v * 2^-7.

#define CSA(s, c, a, b, d)            \
    do {                              \
        unsigned _x = (a) ^ (b);      \
        s = _x ^ (d);                 \
        c = ((a) & (b)) | (_x & (d)); \
    } while (0)

__device__ __forceinline__ unsigned mkmask(float v) {
    // round-half-even int in [-2^22, 2^22] via magic constant (monotone
    // beyond, so the clamp still lands on the right side for any input)
    float r = fmaf(v, 128.0f, 12582912.0f);  // 1.5 * 2^23
    int q = __float_as_int(r) - 0x4B400000;
    q = max(-32768, min(32767, q));
    unsigned u  = (unsigned)q;
    unsigned u3 = u * 3u;
    unsigned nz = ((u3 ^ u) >> 1) & 0xFFFFu;
    unsigned m  = ((u & ~u3) >> 1) & 0xFFFFu;
    return nz | (m << 16);
}

// float4-unit swizzle: conflict-free for both the coalesced (t + 128k) and
// the per-thread (4t + i) access patterns.
__device__ __forceinline__ int swz(int u) { return u ^ ((u >> 3) & 7); }

__global__ void __launch_bounds__(128)
booth_group_quant_kernel(const float4* __restrict__ x,
                         float4* __restrict__ out,
                         int n4 /* float4 count */) {
    __shared__ float4 sin[512];
    __shared__ float4 sou[512];
    const int t = threadIdx.x;
    const int base4 = blockIdx.x * 512;

    // ---- coalesced load -> swizzled smem ----
#pragma unroll
    for (int k = 0; k < 4; ++k) {
        int idx = base4 + k * 128 + t;
        float4 v = make_float4(0.f, 0.f, 0.f, 0.f);
        if (idx < n4) v = x[idx];
        sin[swz(k * 128 + t)] = v;
    }
    __syncthreads();

    float4 f0 = sin[swz(t * 4 + 0)];
    float4 f1 = sin[swz(t * 4 + 1)];
    float4 f2 = sin[swz(t * 4 + 2)];
    float4 f3 = sin[swz(t * 4 + 3)];

    unsigned pk[16];
    pk[0]  = mkmask(f0.x); pk[1]  = mkmask(f0.y);
    pk[2]  = mkmask(f0.z); pk[3]  = mkmask(f0.w);
    pk[4]  = mkmask(f1.x); pk[5]  = mkmask(f1.y);
    pk[6]  = mkmask(f1.z); pk[7]  = mkmask(f1.w);
    pk[8]  = mkmask(f2.x); pk[9]  = mkmask(f2.y);
    pk[10] = mkmask(f2.z); pk[11] = mkmask(f2.w);
    pk[12] = mkmask(f3.x); pk[13] = mkmask(f3.y);
    pk[14] = mkmask(f3.z); pk[15] = mkmask(f3.w);

    // ---- CSA tree: per-exponent column counts as 5 bit-planes ----
    unsigned P0, P1, P2, P3, P4;
    {
        unsigned s1, c1, s2, c2, s3, c3, s4, c4, s5, c5, s6, c6, s7, c7;
        CSA(s1, c1, pk[0], pk[1], pk[2]);
        CSA(s2, c2, pk[3], pk[4], pk[5]);
        CSA(s3, c3, pk[6], pk[7], pk[8]);
        CSA(s4, c4, pk[9], pk[10], pk[11]);
        CSA(s5, c5, pk[12], pk[13], pk[14]);
        CSA(s6, c6, s1, s2, s3);
        CSA(s7, c7, s4, s5, pk[15]);
        P0 = s6 ^ s7;
        unsigned h1 = s6 & s7;
        unsigned sA, cA, sB, cB, sC, cC, sD, cD;
        CSA(sA, cA, c1, c2, c3);
        CSA(sB, cB, c4, c5, c6);
        CSA(sC, cC, c7, h1, sA);
        P1 = sB ^ sC;
        unsigned h2 = sB & sC;
        CSA(sD, cD, cA, cB, cC);
        P2 = sD ^ h2;
        unsigned h3 = sD & h2;
        P3 = cD ^ h3;
        P4 = cD & h3;
        P0 &= 0xFFFFu; P1 &= 0xFFFFu; P2 &= 0xFFFFu; P3 &= 0xFFFFu; P4 &= 0xFFFFu;
    }

    // ---- binary search: largest t in [0,15] with S(t) >= 8; S(16)=0 ----
    int lo = 0, hi = 16, chi = 0;
#pragma unroll
    for (int it = 0; it < 4; ++it) {
        int m = (lo + hi) >> 1;
        int s = __popc(P0 >> m) + 2 * __popc(P1 >> m) + 4 * __popc(P2 >> m) +
                8 * __popc(P3 >> m) + 16 * __popc(P4 >> m);
        if (s >= 8) lo = m; else { hi = m; chi = s; }
    }
    const int tt = lo;
    const int r  = 8 - chi;                              // slots at level t
    const unsigned hm = (0xFFFFu << (tt + 1)) & 0xFFFFu; // exponents > t

    // ---- level-t bit word across elements ----
    unsigned B = 0;
#pragma unroll
    for (int j = 0; j < 16; ++j) B |= ((pk[j] >> tt) & 1u) << j;

    // ---- per-element keep (independent prefix-popc) + reconstruct ----
#define RECON(j)                                                        \
    ({                                                                  \
        unsigned _w   = pk[j];                                          \
        unsigned _bt  = (B >> (j)) & 1u;                                \
        int _pc       = __popc(B & ((1u << (j)) - 1u));                 \
        unsigned _tk  = (_pc < r) ? _bt : 0u;                           \
        unsigned _k   = (_w & hm) | (_tk << tt);                        \
        unsigned _km  = _k & (_w >> 16);                                \
        (float)((int)_k - 2 * (int)_km) * 0.0078125f;                   \
    })

    {
        float4 o;
        o.x = RECON(0);  o.y = RECON(1);  o.z = RECON(2);  o.w = RECON(3);
        sou[swz(t * 4 + 0)] = o;
        o.x = RECON(4);  o.y = RECON(5);  o.z = RECON(6);  o.w = RECON(7);
        sou[swz(t * 4 + 1)] = o;
        o.x = RECON(8);  o.y = RECON(9);  o.z = RECON(10); o.w = RECON(11);
        sou[swz(t * 4 + 2)] = o;
        o.x = RECON(12); o.y = RECON(13); o.z = RECON(14); o.w = RECON(15);
        sou[swz(t * 4 + 3)] = o;
    }
#undef RECON
    __syncthreads();

    // ---- swizzled smem -> coalesced store ----
#pragma unroll
    for (int k = 0; k < 4; ++k) {
        int idx = base4 + k * 128 + t;
        if (idx < n4) out[idx] = sou[swz(k * 128 + t)];
    }
}

extern "C" void kernel_launch(void* const* d_in, const int* in_sizes, int n_in,
                              void* d_out, int out_size) {
    const float* x = (const float*)d_in[0];
    float* out = (float*)d_out;
    int n = in_sizes[0];
    int n4 = n >> 2;                    // float4 count (16B units)
    int grid = (n4 + 511) / 512;        // 512 float4 per block (128 groups)
    booth_group_quant_kernel<<<grid, 128>>>(
        (const float4*)x, (float4*)out, n4);
}

// round 6
// speedup vs baseline: 1.3343x; 1.1343x over previous
#include <cuda_runtime.h>
#include <cstdint>

// BoothGroupQuant, round 6: R3 core (thread = group of 16, direct gmem,
// serial rank walk) with an instruction diet:
//  - no clamp (input range makes it inert), magic-constant round-half-even
//  - mask-free NAF extraction (high bits provably clean for |q| < 2^15)
//  - 3-instr pk pack:  pk = (m<<15) | (xh>>1)   (m bit0 provably 0)
//  - fused keep-mask reconstruction (taken bit read back from k)
//
//   q  = round_half_even(x*128)
//   nz = (3q ^ q) >> 1          (NAF nonzero-digit positions, 16-bit)
//   M  = (q & ~3q) >> 1         (-1 digit positions, 16-bit)
//   keep 8 largest-exponent digits per 16-elem group (ties at threshold
//   exponent t in ascending element order); v = k - 2*(k&M); out = v*2^-7.

#define CSA(s, c, a, b, d)            \
    do {                              \
        unsigned _x = (a) ^ (b);      \
        s = _x ^ (d);                 \
        c = ((a) & (b)) | (_x & (d)); \
    } while (0)

__device__ __forceinline__ unsigned mkmask(float v) {
    // round-half-even to int via magic constant (exact for |v*128| < 2^22)
    float r = fmaf(v, 128.0f, 12582912.0f);          // 1.5 * 2^23
    int q = __float_as_int(r) - 0x4B400000;
    unsigned u  = (unsigned)q;
    unsigned u3 = u * 3u;
    unsigned xh = u3 ^ u;        // bit0 always 0; bits 1..16 = nz<<1; high clean
    unsigned m  = u & ~u3;       // bit0 always 0; bits 1..16 = M<<1;  high clean
    return (m << 15) | (xh >> 1);  // pk = nz | (M << 16)
}

__global__ void __launch_bounds__(128)
booth_group_quant_kernel(const float4* __restrict__ x,
                         float4* __restrict__ out,
                         int ngroups) {
    const int g = blockIdx.x * blockDim.x + threadIdx.x;
    if (g >= ngroups) return;

    const float4* __restrict__ xv = x + (size_t)g * 4;
    float4 f0 = xv[0], f1 = xv[1], f2 = xv[2], f3 = xv[3];

    unsigned pk[16];
    pk[0]  = mkmask(f0.x); pk[1]  = mkmask(f0.y);
    pk[2]  = mkmask(f0.z); pk[3]  = mkmask(f0.w);
    pk[4]  = mkmask(f1.x); pk[5]  = mkmask(f1.y);
    pk[6]  = mkmask(f1.z); pk[7]  = mkmask(f1.w);
    pk[8]  = mkmask(f2.x); pk[9]  = mkmask(f2.y);
    pk[10] = mkmask(f2.z); pk[11] = mkmask(f2.w);
    pk[12] = mkmask(f3.x); pk[13] = mkmask(f3.y);
    pk[14] = mkmask(f3.z); pk[15] = mkmask(f3.w);

    // ---- CSA tree: per-exponent column counts as 5 bit-planes ----
    // (high halves carry M garbage; stripped once before the search)
    unsigned P0, P1, P2, P3, P4;
    {
        unsigned s1, c1, s2, c2, s3, c3, s4, c4, s5, c5, s6, c6, s7, c7;
        CSA(s1, c1, pk[0], pk[1], pk[2]);
        CSA(s2, c2, pk[3], pk[4], pk[5]);
        CSA(s3, c3, pk[6], pk[7], pk[8]);
        CSA(s4, c4, pk[9], pk[10], pk[11]);
        CSA(s5, c5, pk[12], pk[13], pk[14]);
        CSA(s6, c6, s1, s2, s3);
        CSA(s7, c7, s4, s5, pk[15]);
        P0 = s6 ^ s7;
        unsigned h1 = s6 & s7;
        unsigned sA, cA, sB, cB, sC, cC, sD, cD;
        CSA(sA, cA, c1, c2, c3);
        CSA(sB, cB, c4, c5, c6);
        CSA(sC, cC, c7, h1, sA);
        P1 = sB ^ sC;
        unsigned h2 = sB & sC;
        CSA(sD, cD, cA, cB, cC);
        P2 = sD ^ h2;
        unsigned h3 = sD & h2;
        P3 = cD ^ h3;
        P4 = cD & h3;
        P0 &= 0xFFFFu; P1 &= 0xFFFFu; P2 &= 0xFFFFu; P3 &= 0xFFFFu; P4 &= 0xFFFFu;
    }

    // ---- binary search: largest t in [0,15] with S(t) >= 8; S(16)=0 ----
    int lo = 0, hi = 16, chi = 0;
#pragma unroll
    for (int it = 0; it < 4; ++it) {
        int m = (lo + hi) >> 1;
        int s = __popc(P0 >> m) + 2 * __popc(P1 >> m) + 4 * __popc(P2 >> m) +
                8 * __popc(P3 >> m) + 16 * __popc(P4 >> m);
        if (s >= 8) lo = m; else { hi = m; chi = s; }
    }
    const int t = lo;
    int rk = 8 - chi;                                    // slots at level t
    const unsigned hm  = (0xFFFFu << (t + 1)) & 0xFFFFu; // exponents > t
    const unsigned hmt = hm | (1u << t);                 // ... plus level t

    // ---- serial rank walk + fused keep-mask + reconstruct ----
#define RECON(j)                                           \
    ({                                                     \
        unsigned _w = pk[j];                               \
        unsigned _k = _w & ((rk > 0) ? hmt : hm);          \
        rk -= (int)((_k >> t) & 1u);                       \
        unsigned _km = _k & (_w >> 16);                    \
        (float)((int)_k - 2 * (int)_km) * 0.0078125f;      \
    })

    float4* __restrict__ ov = out + (size_t)g * 4;
    {
        float4 o;
        o.x = RECON(0);  o.y = RECON(1);  o.z = RECON(2);  o.w = RECON(3);
        ov[0] = o;
        o.x = RECON(4);  o.y = RECON(5);  o.z = RECON(6);  o.w = RECON(7);
        ov[1] = o;
        o.x = RECON(8);  o.y = RECON(9);  o.z = RECON(10); o.w = RECON(11);
        ov[2] = o;
        o.x = RECON(12); o.y = RECON(13); o.z = RECON(14); o.w = RECON(15);
        ov[3] = o;
    }
#undef RECON
}

extern "C" void kernel_launch(void* const* d_in, const int* in_sizes, int n_in,
                              void* d_out, int out_size) {
    const float* x = (const float*)d_in[0];
    float* out = (float*)d_out;
    int n = in_sizes[0];
    int ngroups = n >> 4;  // 16 elements per group
    int block = 128;
    int grid = (ngroups + block - 1) / block;
    booth_group_quant_kernel<<<grid, block>>>(
        (const float4*)x, (float4*)out, ngroups);
}